// round 12
// baseline (speedup 1.0000x reference)
#include <cuda_runtime.h>
#include <cuda_bf16.h>
#include <math.h>
#include <stdint.h>

#define H 96
#define W 96
#define HW (H*W)          // 9216
#define CIN 256
#define B 2
#define KK 9
#define GK (CIN*KK)       // 2304
#define GM 256
#define GN HW

// ---------------- scratch (static device allocations) -------------------------
__device__ float g_col[(size_t)B * GK * HW];        // im2col, tf32-rounded fp32
__device__ float g_om[(size_t)B * 27 * HW];
__device__ float g_om_part[8ull * B * 27 * HW];
__device__ float g_h[(size_t)B * CIN * HW];
__device__ float g_wtf[(size_t)GM * GK];            // W, tf32-rounded fp32

// ---------------- helpers ------------------------------------------------------
__device__ __forceinline__ float to_tf32(float x) {
    float r; asm("cvt.rna.tf32.f32 %0, %1;" : "=f"(r) : "f"(x)); return r;
}
__device__ __forceinline__ uint32_t sm_u32(const void* p) {
    uint32_t a;
    asm("{ .reg .u64 t; cvta.to.shared.u64 t, %1; cvt.u32.u64 %0, t; }" : "=r"(a) : "l"(p));
    return a;
}
__device__ __forceinline__ void cpasync16(uint32_t dst, const void* src) {
    asm volatile("cp.async.cg.shared.global [%0], [%1], 16;" :: "r"(dst), "l"(src));
}
#define CP_COMMIT() asm volatile("cp.async.commit_group;" ::: "memory")
#define CP_WAIT1()  asm volatile("cp.async.wait_group 1;" ::: "memory")

#define MMA_TF32(d, a, bb) \
    asm volatile("mma.sync.aligned.m16n8k8.row.col.f32.tf32.tf32.f32 " \
        "{%0,%1,%2,%3}, {%4,%5,%6,%7}, {%8,%9}, {%0,%1,%2,%3};" \
        : "+f"((d)[0]), "+f"((d)[1]), "+f"((d)[2]), "+f"((d)[3]) \
        : "r"((a)[0]), "r"((a)[1]), "r"((a)[2]), "r"((a)[3]), \
          "r"((bb)[0]), "r"((bb)[1]))

// ---------------- offset conv (SMEM-tiled): grid (36,8,B), block 256 ----------
__global__ void offset_conv_kernel(const float* __restrict__ x,
                                   const float* __restrict__ w_off,
                                   float* __restrict__ om_part) {
    int b = blockIdx.z, chunk = blockIdx.y, tile = blockIdx.x;
    int h0 = (tile / 6) * 16, w0 = (tile % 6) * 16;
    int ty = threadIdx.x >> 4, tx = threadIdx.x & 15;

    float acc[27];
#pragma unroll
    for (int i = 0; i < 27; i++) acc[i] = 0.f;

    __shared__ float ws[243];
    __shared__ float xt[18 * 18];
    const float* xb = x + (size_t)b * CIN * HW;
    int c0 = chunk * 32;
    for (int c = c0; c < c0 + 32; c++) {
        __syncthreads();
        if (threadIdx.x < 243) {
            int oc = threadIdx.x / 9, k = threadIdx.x % 9;
            ws[threadIdx.x] = w_off[((size_t)oc * CIN + c) * 9 + k];
        }
        const float* xc = xb + (size_t)c * HW;
        for (int idx = threadIdx.x; idx < 324; idx += 256) {
            int yy = h0 - 1 + idx / 18, xx = w0 - 1 + idx % 18;
            xt[idx] = (yy >= 0 && yy < H && xx >= 0 && xx < W) ? xc[yy * W + xx] : 0.f;
        }
        __syncthreads();
        float xv[9];
#pragma unroll
        for (int k = 0; k < 9; k++)
            xv[k] = xt[(ty + k / 3) * 18 + tx + k % 3];
#pragma unroll
        for (int oc = 0; oc < 27; oc++)
#pragma unroll
            for (int k = 0; k < 9; k++)
                acc[oc] = fmaf(ws[oc * 9 + k], xv[k], acc[oc]);
    }
    int h = h0 + ty, w = w0 + tx;
    float* dst = om_part + ((size_t)chunk * B * 27 + (size_t)b * 27) * HW + h * W + w;
#pragma unroll
    for (int oc = 0; oc < 27; oc++) dst[(size_t)oc * HW] = acc[oc];
}

__global__ void reduce_om_kernel(const float* __restrict__ part,
                                 const float* __restrict__ b_off,
                                 float* __restrict__ om) {
    int i = blockIdx.x * 256 + threadIdx.x;
    const int N = B * 27 * HW;
    int oc = (i / HW) % 27;
    float s = b_off[oc];
#pragma unroll
    for (int j = 0; j < 8; j++) s += part[(size_t)j * N + i];
    om[i] = s;
}

// ---------------- deformable im2col (tf32, 2 pixels/thread) -------------------
// grid (HW/512, 9*4, B), block 256; y encodes (cchunk, k); 64 channels/block
__global__ void sample_kernel(const float* __restrict__ x,
                              const float* __restrict__ om,
                              float* __restrict__ col) {
    int b = blockIdx.z;
    int k = blockIdx.y % KK;
    int cc = blockIdx.y / KK;
    int pa = blockIdx.x * 512 + 2 * threadIdx.x;

    const float* omb = om + (size_t)b * 27 * HW;
    float2 dy2 = *(const float2*)(omb + (size_t)(2 * k) * HW + pa);
    float2 dx2 = *(const float2*)(omb + (size_t)(2 * k + 1) * HW + pa);
    float2 mm2 = *(const float2*)(omb + (size_t)(18 + k) * HW + pa);

    float wq[2][4];
    int   iq[2][4];
#pragma unroll
    for (int px = 0; px < 2; px++) {
        int p = pa + px;
        int h = p / W, w = p % W;
        float dyv = px ? dy2.y : dy2.x;
        float dxv = px ? dx2.y : dx2.x;
        float mv  = px ? mm2.y : mm2.x;
        mv = 1.f / (1.f + __expf(-mv));

        float ys = (float)(h + k / 3 - 1) + dyv;
        float xs = (float)(w + k % 3 - 1) + dxv;
        float y0f = floorf(ys), x0f = floorf(xs);
        int y0 = (int)y0f, x0 = (int)x0f;
        int y1 = y0 + 1, x1 = x0 + 1;
        float wy1 = ys - y0f, wx1 = xs - x0f;
        float wy0 = 1.f - wy1, wx0 = 1.f - wx1;

        bool vy0 = (y0 >= 0) & (y0 < H), vy1 = (y1 >= 0) & (y1 < H);
        bool vx0 = (x0 >= 0) & (x0 < W), vx1 = (x1 >= 0) & (x1 < W);
        int yc0 = min(max(y0, 0), H - 1), yc1 = min(max(y1, 0), H - 1);
        int xc0 = min(max(x0, 0), W - 1), xc1 = min(max(x1, 0), W - 1);

        wq[px][0] = wy0 * wx0 * ((vy0 & vx0) ? mv : 0.f);
        wq[px][1] = wy0 * wx1 * ((vy0 & vx1) ? mv : 0.f);
        wq[px][2] = wy1 * wx0 * ((vy1 & vx0) ? mv : 0.f);
        wq[px][3] = wy1 * wx1 * ((vy1 & vx1) ? mv : 0.f);
        iq[px][0] = yc0 * W + xc0;
        iq[px][1] = yc0 * W + xc1;
        iq[px][2] = yc1 * W + xc0;
        iq[px][3] = yc1 * W + xc1;
    }

    const float* xb = x + (size_t)b * CIN * HW;
    float* colb = col + (size_t)b * GK * HW + (size_t)k * HW + pa;
    int cbeg = cc * 64, cend = cbeg + 64;
#pragma unroll 4
    for (int c = cbeg; c < cend; c++) {
        const float* xc = xb + (size_t)c * HW;
        float v0 = wq[0][0] * __ldg(xc + iq[0][0]) + wq[0][1] * __ldg(xc + iq[0][1])
                 + wq[0][2] * __ldg(xc + iq[0][2]) + wq[0][3] * __ldg(xc + iq[0][3]);
        float v1 = wq[1][0] * __ldg(xc + iq[1][0]) + wq[1][1] * __ldg(xc + iq[1][1])
                 + wq[1][2] * __ldg(xc + iq[1][2]) + wq[1][3] * __ldg(xc + iq[1][3]);
        float2 o;
        o.x = to_tf32(v0);
        o.y = to_tf32(v1);
        *(float2*)(colb + (size_t)c * KK * HW) = o;
    }
}

// ---------------- weight tf32 pre-rounding ------------------------------------
__global__ void wcvt_kernel(const float* __restrict__ w, float* __restrict__ wt) {
    int i = blockIdx.x * 256 + threadIdx.x;
    wt[i] = to_tf32(w[i]);
}

// ---------------- tf32 GEMM: M=256 x N=128 CTA tile, 3-stage, 1 sync/chunk ----
#define NCH (GK / 32)                 // 72
#define AS_STRIDE 36                  // 32 + 4 pad (floats)
#define BS_STRIDE 132                 // 128 + 4 pad
#define A_FLOATS (256 * AS_STRIDE)    // 9216
#define B_FLOATS (32 * BS_STRIDE)     // 4224
#define STG_FLOATS (A_FLOATS + B_FLOATS)      // 13440 (53760 B)
#define SM_BYTES (3 * STG_FLOATS * 4)         // 161280 B

__device__ __forceinline__ void load_stage(uint32_t sa, int k0, int tid,
                                           const float* A, const float* Bg) {
    // A: 256 rows x 32 k; thread = row, 8 x 16B chunks
    {
        const float* arow = A + (size_t)tid * GK + k0;
        uint32_t abase = sa + (uint32_t)(tid * AS_STRIDE) * 4;
#pragma unroll
        for (int j = 0; j < 8; j++)
            cpasync16(abase + j * 16, arow + j * 4);
    }
    // B: 32 rows(k) x 128 p; thread -> row = tid>>3, 4 chunks c=(tid&7)*4+j
    {
        int brow = tid >> 3;
        const float* br = Bg + (size_t)(k0 + brow) * GN;
        uint32_t bbase = sa + (uint32_t)(A_FLOATS + brow * BS_STRIDE) * 4;
        int c0 = (tid & 7) * 4;
#pragma unroll
        for (int j = 0; j < 4; j++) {
            int c = c0 + j;
            cpasync16(bbase + c * 16, br + c * 4);
        }
    }
}

__global__ __launch_bounds__(256, 1)
void gemm_tf32_kernel(const float* __restrict__ A,     // g_wtf [GM][GK]
                      const float* __restrict__ Bm,    // col   [B][GK][GN]
                      float* __restrict__ Cc) {        // out   [B][GM][GN]
    extern __shared__ float sm[];
    uint32_t smb = sm_u32(sm);
    const int tid = threadIdx.x;
    const int lane = tid & 31;
    const int wrp = tid >> 5;
    const int b = blockIdx.y;
    const int p0 = blockIdx.x * 128;

    const float* Bg = Bm + (size_t)b * GK * GN + p0;

    // prologue: chunks 0,1 into stages 0,1
    load_stage(smb, 0, tid, A, Bg);
    CP_COMMIT();
    load_stage(smb + STG_FLOATS * 4, 32, tid, A, Bg);
    CP_COMMIT();

    const int wm = (wrp >> 1) * 64;   // warp m offset: 0,64,128,192
    const int wn = (wrp & 1) * 64;    // warp n offset: 0,64
    const int ar = lane >> 2, ac = lane & 3;

    float acc[4][8][4];
#pragma unroll
    for (int i = 0; i < 4; i++)
#pragma unroll
        for (int j = 0; j < 8; j++)
#pragma unroll
            for (int q = 0; q < 4; q++) acc[i][j][q] = 0.f;

    for (int ch = 0; ch < NCH; ch++) {
        CP_WAIT1();          // chunk ch resident
        __syncthreads();     // all threads done with buffer (ch-1)%3; ch visible

        // issue loads for chunk ch+2 into buffer (ch+2)%3 == (ch-1)%3
        if (ch + 2 < NCH)
            load_stage(smb + (uint32_t)((ch + 2) % 3) * STG_FLOATS * 4,
                       (ch + 2) * 32, tid, A, Bg);
        CP_COMMIT();         // unconditional: keeps wait_group accounting exact

        const float* as = sm + (ch % 3) * STG_FLOATS;
        const float* bs = as + A_FLOATS;
        const uint32_t* asu = (const uint32_t*)as;
        const uint32_t* bsu = (const uint32_t*)bs;

#pragma unroll
        for (int ks = 0; ks < 4; ks++) {
            uint32_t afr[4][4], bfr[8][2];
#pragma unroll
            for (int mf = 0; mf < 4; mf++) {
                int r = wm + mf * 16 + ar;
                int c = ks * 8 + ac;
                afr[mf][0] = asu[r * AS_STRIDE + c];
                afr[mf][1] = asu[(r + 8) * AS_STRIDE + c];
                afr[mf][2] = asu[r * AS_STRIDE + c + 4];
                afr[mf][3] = asu[(r + 8) * AS_STRIDE + c + 4];
            }
#pragma unroll
            for (int nf = 0; nf < 8; nf++) {
                int c = wn + nf * 8 + ar;
                bfr[nf][0] = bsu[(ks * 8 + ac) * BS_STRIDE + c];
                bfr[nf][1] = bsu[(ks * 8 + 4 + ac) * BS_STRIDE + c];
            }
#pragma unroll
            for (int mf = 0; mf < 4; mf++)
#pragma unroll
                for (int nf = 0; nf < 8; nf++)
                    MMA_TF32(acc[mf][nf], afr[mf], bfr[nf]);
        }
    }

    // epilogue: ReLU + float2 stores
    float* Cb = Cc + (size_t)b * GM * GN;
    const int pbase = p0 + wn;
#pragma unroll
    for (int mf = 0; mf < 4; mf++) {
#pragma unroll
        for (int nf = 0; nf < 8; nf++) {
            int o = wm + mf * 16 + ar;
            int p = pbase + nf * 8 + 2 * ac;
            float2 v0, v1;
            v0.x = fmaxf(acc[mf][nf][0], 0.f);
            v0.y = fmaxf(acc[mf][nf][1], 0.f);
            v1.x = fmaxf(acc[mf][nf][2], 0.f);
            v1.y = fmaxf(acc[mf][nf][3], 0.f);
            *(float2*)(Cb + (size_t)o * GN + p) = v0;
            *(float2*)(Cb + (size_t)(o + 8) * GN + p) = v1;
        }
    }
}

// ---------------- host side ----------------------------------------------------
static void run_layer(const float* xin, const float* w_off, const float* b_off,
                      const float* wmain, float* outp,
                      float* col, float* om, float* om_part, float* wtf) {
    dim3 gOff(36, 8, B);
    offset_conv_kernel<<<gOff, 256>>>(xin, w_off, om_part);
    reduce_om_kernel<<<(B * 27 * HW) / 256, 256>>>(om_part, b_off, om);
    wcvt_kernel<<<(GM * GK) / 256, 256>>>(wmain, wtf);
    dim3 gSamp(HW / 512, KK * 4, B);
    sample_kernel<<<gSamp, 256>>>(xin, om, col);
    dim3 gGemm(GN / 128, B);
    gemm_tf32_kernel<<<gGemm, 256, SM_BYTES>>>(wtf, col, outp);
}

extern "C" void kernel_launch(void* const* d_in, const int* in_sizes, int n_in,
                              void* d_out, int out_size) {
    const float* x      = (const float*)d_in[0];
    const float* w_off0 = (const float*)d_in[1];
    const float* b_off0 = (const float*)d_in[2];
    const float* w0     = (const float*)d_in[3];
    const float* w_off1 = (const float*)d_in[4];
    const float* b_off1 = (const float*)d_in[5];
    const float* w1     = (const float*)d_in[6];
    float* out = (float*)d_out;

    static bool attr_set = false;
    if (!attr_set) {
        cudaFuncSetAttribute(gemm_tf32_kernel,
                             cudaFuncAttributeMaxDynamicSharedMemorySize, SM_BYTES);
        attr_set = true;
    }

    float *col, *om, *om_part, *hbuf, *wtf;
    cudaGetSymbolAddress((void**)&col,     g_col);
    cudaGetSymbolAddress((void**)&om,      g_om);
    cudaGetSymbolAddress((void**)&om_part, g_om_part);
    cudaGetSymbolAddress((void**)&hbuf,    g_h);
    cudaGetSymbolAddress((void**)&wtf,     g_wtf);

    run_layer(x,    w_off0, b_off0, w0, hbuf, col, om, om_part, wtf);
    run_layer(hbuf, w_off1, b_off1, w1, out,  col, om, om_part, wtf);
}

// round 13
// speedup vs baseline: 1.1428x; 1.1428x over previous
#include <cuda_runtime.h>
#include <cuda_bf16.h>
#include <math.h>
#include <stdint.h>

#define H 96
#define W 96
#define HW (H*W)          // 9216
#define CIN 256
#define B 2
#define KK 9
#define GK (CIN*KK)       // 2304
#define GM 256
#define GN HW

// ---------------- scratch (static device allocations) -------------------------
__device__ float g_col[(size_t)B * GK * HW];        // im2col, tf32-rounded fp32
__device__ float g_om[(size_t)B * 27 * HW];
__device__ float g_om_part[8ull * B * 27 * HW];
__device__ float g_h[(size_t)B * CIN * HW];
__device__ float g_wtf[(size_t)GM * GK];            // W, tf32-rounded fp32

// ---------------- helpers ------------------------------------------------------
__device__ __forceinline__ float to_tf32(float x) {
    float r; asm("cvt.rna.tf32.f32 %0, %1;" : "=f"(r) : "f"(x)); return r;
}
__device__ __forceinline__ uint32_t sm_u32(const void* p) {
    uint32_t a;
    asm("{ .reg .u64 t; cvta.to.shared.u64 t, %1; cvt.u32.u64 %0, t; }" : "=r"(a) : "l"(p));
    return a;
}
__device__ __forceinline__ void cpasync16(uint32_t dst, const void* src) {
    asm volatile("cp.async.cg.shared.global [%0], [%1], 16;" :: "r"(dst), "l"(src));
}
#define CP_COMMIT() asm volatile("cp.async.commit_group;" ::: "memory")
#define CP_WAIT1()  asm volatile("cp.async.wait_group 1;" ::: "memory")

#define MMA_TF32(d, a, bb) \
    asm volatile("mma.sync.aligned.m16n8k8.row.col.f32.tf32.tf32.f32 " \
        "{%0,%1,%2,%3}, {%4,%5,%6,%7}, {%8,%9}, {%0,%1,%2,%3};" \
        : "+f"((d)[0]), "+f"((d)[1]), "+f"((d)[2]), "+f"((d)[3]) \
        : "r"((a)[0]), "r"((a)[1]), "r"((a)[2]), "r"((a)[3]), \
          "r"((bb)[0]), "r"((bb)[1]))

// ---------------- offset conv (SMEM-tiled): grid (36,8,B), block 256 ----------
__global__ void offset_conv_kernel(const float* __restrict__ x,
                                   const float* __restrict__ w_off,
                                   float* __restrict__ om_part) {
    int b = blockIdx.z, chunk = blockIdx.y, tile = blockIdx.x;
    int h0 = (tile / 6) * 16, w0 = (tile % 6) * 16;
    int ty = threadIdx.x >> 4, tx = threadIdx.x & 15;

    float acc[27];
#pragma unroll
    for (int i = 0; i < 27; i++) acc[i] = 0.f;

    __shared__ float ws[243];
    __shared__ float xt[18 * 18];
    const float* xb = x + (size_t)b * CIN * HW;
    int c0 = chunk * 32;
    for (int c = c0; c < c0 + 32; c++) {
        __syncthreads();
        if (threadIdx.x < 243) {
            int oc = threadIdx.x / 9, k = threadIdx.x % 9;
            ws[threadIdx.x] = w_off[((size_t)oc * CIN + c) * 9 + k];
        }
        const float* xc = xb + (size_t)c * HW;
        for (int idx = threadIdx.x; idx < 324; idx += 256) {
            int yy = h0 - 1 + idx / 18, xx = w0 - 1 + idx % 18;
            xt[idx] = (yy >= 0 && yy < H && xx >= 0 && xx < W) ? xc[yy * W + xx] : 0.f;
        }
        __syncthreads();
        float xv[9];
#pragma unroll
        for (int k = 0; k < 9; k++)
            xv[k] = xt[(ty + k / 3) * 18 + tx + k % 3];
#pragma unroll
        for (int oc = 0; oc < 27; oc++)
#pragma unroll
            for (int k = 0; k < 9; k++)
                acc[oc] = fmaf(ws[oc * 9 + k], xv[k], acc[oc]);
    }
    int h = h0 + ty, w = w0 + tx;
    float* dst = om_part + ((size_t)chunk * B * 27 + (size_t)b * 27) * HW + h * W + w;
#pragma unroll
    for (int oc = 0; oc < 27; oc++) dst[(size_t)oc * HW] = acc[oc];
}

__global__ void reduce_om_kernel(const float* __restrict__ part,
                                 const float* __restrict__ b_off,
                                 float* __restrict__ om) {
    int i = blockIdx.x * 256 + threadIdx.x;
    const int N = B * 27 * HW;
    int oc = (i / HW) % 27;
    float s = b_off[oc];
#pragma unroll
    for (int j = 0; j < 8; j++) s += part[(size_t)j * N + i];
    om[i] = s;
}

// ---------------- deformable im2col (tf32 output, channel-split) --------------
// grid (36, 9*4, B): y encodes (cchunk, k); each block does 64 channels
__global__ void sample_kernel(const float* __restrict__ x,
                              const float* __restrict__ om,
                              float* __restrict__ col) {
    int b = blockIdx.z;
    int k = blockIdx.y % KK;
    int cc = blockIdx.y / KK;
    int p = blockIdx.x * 256 + threadIdx.x;
    int h = p / W, w = p % W;

    const float* omb = om + (size_t)b * 27 * HW;
    float dy = omb[(size_t)(2 * k) * HW + p];
    float dx = omb[(size_t)(2 * k + 1) * HW + p];
    float m  = omb[(size_t)(18 + k) * HW + p];
    m = 1.f / (1.f + __expf(-m));

    float ys = (float)(h + k / 3 - 1) + dy;
    float xs = (float)(w + k % 3 - 1) + dx;
    float y0f = floorf(ys), x0f = floorf(xs);
    int y0 = (int)y0f, x0 = (int)x0f;
    int y1 = y0 + 1, x1 = x0 + 1;
    float wy1 = ys - y0f, wx1 = xs - x0f;
    float wy0 = 1.f - wy1, wx0 = 1.f - wx1;

    bool vy0 = (y0 >= 0) & (y0 < H), vy1 = (y1 >= 0) & (y1 < H);
    bool vx0 = (x0 >= 0) & (x0 < W), vx1 = (x1 >= 0) & (x1 < W);
    int yc0 = min(max(y0, 0), H - 1), yc1 = min(max(y1, 0), H - 1);
    int xc0 = min(max(x0, 0), W - 1), xc1 = min(max(x1, 0), W - 1);

    float w00 = wy0 * wx0 * ((vy0 & vx0) ? m : 0.f);
    float w01 = wy0 * wx1 * ((vy0 & vx1) ? m : 0.f);
    float w10 = wy1 * wx0 * ((vy1 & vx0) ? m : 0.f);
    float w11 = wy1 * wx1 * ((vy1 & vx1) ? m : 0.f);

    int i00 = yc0 * W + xc0, i01 = yc0 * W + xc1;
    int i10 = yc1 * W + xc0, i11 = yc1 * W + xc1;

    const float* xb = x + (size_t)b * CIN * HW;
    float* colb = col + (size_t)b * GK * HW + (size_t)k * HW + p;
    int cbeg = cc * 64, cend = cbeg + 64;
#pragma unroll 8
    for (int c = cbeg; c < cend; c++) {
        const float* xc = xb + (size_t)c * HW;
        float v = w00 * __ldg(xc + i00) + w01 * __ldg(xc + i01)
                + w10 * __ldg(xc + i10) + w11 * __ldg(xc + i11);
        colb[(size_t)c * KK * HW] = to_tf32(v);
    }
}

// ---------------- weight tf32 pre-rounding ------------------------------------
__global__ void wcvt_kernel(const float* __restrict__ w, float* __restrict__ wt) {
    int i = blockIdx.x * 256 + threadIdx.x;
    wt[i] = to_tf32(w[i]);
}

// ---------------- tf32 GEMM: 128x128 tile, 3-stage pipeline, 1 sync/chunk -----
// grid (GN/128, GM/128, B), block 256 (8 warps), warp tile 64x32 (R8-proven).
#define NCH (GK / 32)                 // 72
#define AS_STRIDE 36                  // 32 + 4 pad (floats)
#define BS_STRIDE 132                 // 128 + 4 pad
#define AS_BUF (128 * AS_STRIDE)      // 4608 floats
#define BS_BUF (32 * BS_STRIDE)       // 4224 floats
#define STG_FLOATS (AS_BUF + BS_BUF)  // 8832 floats = 35328 B
#define SM_BYTES (3 * STG_FLOATS * 4) // 105984 B (occupancy 2 preserved)

__device__ __forceinline__ void load_stage(uint32_t sa, int k0, int tid,
                                           const float* Ag, const float* Bg) {
    // A: 128 rows x 32 k (same thread map as R8)
    int am = tid >> 3, aq = tid & 7;
#pragma unroll
    for (int i = 0; i < 4; i++) {
        int m = am + i * 32;
        cpasync16(sa + (uint32_t)(m * AS_STRIDE + aq * 4) * 4,
                  Ag + (size_t)m * GK + k0 + aq * 4);
    }
    // B: 32 rows(k) x 128 p
    int bk = tid >> 5, bq = tid & 31;
#pragma unroll
    for (int i = 0; i < 4; i++) {
        int k = bk + i * 8;
        cpasync16(sa + (uint32_t)(AS_BUF + k * BS_STRIDE + bq * 4) * 4,
                  Bg + (size_t)(k0 + k) * GN + bq * 4);
    }
}

__global__ __launch_bounds__(256, 2)
void gemm_tf32_kernel(const float* __restrict__ A,     // g_wtf [GM][GK]
                      const float* __restrict__ Bm,    // col   [B][GK][GN]
                      float* __restrict__ Cc) {        // out   [B][GM][GN]
    extern __shared__ float sm[];
    uint32_t smb = sm_u32(sm);
    const int tid = threadIdx.x;
    const int lane = tid & 31;
    const int wrp = tid >> 5;
    const int b = blockIdx.z;
    const int p0 = blockIdx.x * 128;
    const int m0 = blockIdx.y * 128;

    const float* Ag = A + (size_t)m0 * GK;
    const float* Bg = Bm + (size_t)b * GK * GN + p0;

    // prologue: chunks 0,1 into stages 0,1
    load_stage(smb, 0, tid, Ag, Bg);
    CP_COMMIT();
    load_stage(smb + STG_FLOATS * 4, 32, tid, Ag, Bg);
    CP_COMMIT();

    const int wm = (wrp >> 2) * 64;
    const int wn = (wrp & 3) * 32;
    const int ar = lane >> 2, ac = lane & 3;

    float acc[4][4][4];
#pragma unroll
    for (int i = 0; i < 4; i++)
#pragma unroll
        for (int j = 0; j < 4; j++)
#pragma unroll
            for (int q = 0; q < 4; q++) acc[i][j][q] = 0.f;

    for (int ch = 0; ch < NCH; ch++) {
        CP_WAIT1();          // chunk ch resident
        __syncthreads();     // all warps done reading buffer (ch+2)%3 (= (ch-1)%3)

        // prefetch chunk ch+2 BEFORE MMA so LDG latency hides under tensor work
        if (ch + 2 < NCH)
            load_stage(smb + (uint32_t)((ch + 2) % 3) * STG_FLOATS * 4,
                       (ch + 2) * 32, tid, Ag, Bg);
        CP_COMMIT();         // unconditional: keeps wait_group accounting exact

        const float* as = sm + (ch % 3) * STG_FLOATS;
        const uint32_t* asu = (const uint32_t*)as;
        const uint32_t* bsu = (const uint32_t*)(as + AS_BUF);

#pragma unroll
        for (int ks = 0; ks < 4; ks++) {
            uint32_t afr[4][4], bfr[4][2];
#pragma unroll
            for (int mf = 0; mf < 4; mf++) {
                int r = wm + mf * 16 + ar;
                int c = ks * 8 + ac;
                afr[mf][0] = asu[r * AS_STRIDE + c];
                afr[mf][1] = asu[(r + 8) * AS_STRIDE + c];
                afr[mf][2] = asu[r * AS_STRIDE + c + 4];
                afr[mf][3] = asu[(r + 8) * AS_STRIDE + c + 4];
            }
#pragma unroll
            for (int nf = 0; nf < 4; nf++) {
                int c = wn + nf * 8 + ar;
                bfr[nf][0] = bsu[(ks * 8 + ac) * BS_STRIDE + c];
                bfr[nf][1] = bsu[(ks * 8 + 4 + ac) * BS_STRIDE + c];
            }
#pragma unroll
            for (int mf = 0; mf < 4; mf++)
#pragma unroll
                for (int nf = 0; nf < 4; nf++)
                    MMA_TF32(acc[mf][nf], afr[mf], bfr[nf]);
        }
    }

    // epilogue: ReLU + float2 stores
    float* Cb = Cc + (size_t)b * GM * GN;
    const int obase = m0 + wm;
    const int pbase = p0 + wn;
#pragma unroll
    for (int mf = 0; mf < 4; mf++) {
#pragma unroll
        for (int nf = 0; nf < 4; nf++) {
            int o = obase + mf * 16 + ar;
            int p = pbase + nf * 8 + 2 * ac;
            float2 v0, v1;
            v0.x = fmaxf(acc[mf][nf][0], 0.f);
            v0.y = fmaxf(acc[mf][nf][1], 0.f);
            v1.x = fmaxf(acc[mf][nf][2], 0.f);
            v1.y = fmaxf(acc[mf][nf][3], 0.f);
            *(float2*)(Cb + (size_t)o * GN + p) = v0;
            *(float2*)(Cb + (size_t)(o + 8) * GN + p) = v1;
        }
    }
}

// ---------------- host side ----------------------------------------------------
static void run_layer(const float* xin, const float* w_off, const float* b_off,
                      const float* wmain, float* outp,
                      float* col, float* om, float* om_part, float* wtf) {
    dim3 gOff(36, 8, B);
    offset_conv_kernel<<<gOff, 256>>>(xin, w_off, om_part);
    reduce_om_kernel<<<(B * 27 * HW) / 256, 256>>>(om_part, b_off, om);
    wcvt_kernel<<<(GM * GK) / 256, 256>>>(wmain, wtf);
    dim3 gSamp(36, KK * 4, B);
    sample_kernel<<<gSamp, 256>>>(xin, om, col);
    dim3 gGemm(GN / 128, GM / 128, B);
    gemm_tf32_kernel<<<gGemm, 256, SM_BYTES>>>(wtf, col, outp);
}

extern "C" void kernel_launch(void* const* d_in, const int* in_sizes, int n_in,
                              void* d_out, int out_size) {
    const float* x      = (const float*)d_in[0];
    const float* w_off0 = (const float*)d_in[1];
    const float* b_off0 = (const float*)d_in[2];
    const float* w0     = (const float*)d_in[3];
    const float* w_off1 = (const float*)d_in[4];
    const float* b_off1 = (const float*)d_in[5];
    const float* w1     = (const float*)d_in[6];
    float* out = (float*)d_out;

    static bool attr_set = false;
    if (!attr_set) {
        cudaFuncSetAttribute(gemm_tf32_kernel,
                             cudaFuncAttributeMaxDynamicSharedMemorySize, SM_BYTES);
        attr_set = true;
    }

    float *col, *om, *om_part, *hbuf, *wtf;
    cudaGetSymbolAddress((void**)&col,     g_col);
    cudaGetSymbolAddress((void**)&om,      g_om);
    cudaGetSymbolAddress((void**)&om_part, g_om_part);
    cudaGetSymbolAddress((void**)&hbuf,    g_h);
    cudaGetSymbolAddress((void**)&wtf,     g_wtf);

    run_layer(x,    w_off0, b_off0, w0, hbuf, col, om, om_part, wtf);
    run_layer(hbuf, w_off1, b_off1, w1, out,  col, om, om_part, wtf);
}